// round 12
// baseline (speedup 1.0000x reference)
#include <cuda_runtime.h>

#define HH 2048
#define WW 2048
#define MW 2047
#define NPIX (HH * WW)

#define CORE 128
#define B0   149           // patch extent: 128 core + 1 (f diff) + 2*10 halo
#define BP   152           // even pitch
#define FAP  130           // f accumulator pitch (129x129 used)
#define NT   960
#define NRUN 949           // 13 a-runs x 73 b-cols
#define ASIZE (B0 * BP)
#define GUARD 1680         // covers deep gated reads AND 151-row staging
#define NACC 24            // ceil(149*149 / NT)

__device__ __forceinline__ float2 lds2(const float* p) {
    return *reinterpret_cast<const float2*>(p);
}
__device__ __forceinline__ void sts2(float* p, float x, float y) {
    *reinterpret_cast<float2*>(p) = make_float2(x, y);
}

// Reassociated 9-term correlation: two partial chains + final add.
#define CORR9(x0,x1,x2,x3,x4,x5,x6,x7,x8)                                  \
    (fmaf(x6, w6, fmaf(x4, w4, fmaf(x2, w2, (x0) * w0))) +                 \
     fmaf(x8, w8, fmaf(x7, w7, fmaf(x5, w5, fmaf(x3, w3, (x1) * w1)))))

// ---------------------------------------------------------------------------
// One fused _compute iteration: 15-row x 6-col rolling window per vertical
// run of 6 quads. Valid slot range iter K: a,b in [K, 74-K].
// ---------------------------------------------------------------------------
template <int K>
__device__ __forceinline__ void iter_step(
    const float* __restrict__ in, float* __restrict__ out,
    float* __restrict__ FA,
    int wio, int a0, int b, int nPack, int mPack, int fmPack, float* fa,
    float w0, float w1, float w2, float w3, float w4,
    float w5, float w6, float w7, float w8,
    float alpha, float bs, float g)
{
    const float* p = in + wio;

    // Prologue: rows 2a0-1, 2a0, 2a0+1, top corners.
    const float2 L0 = lds2(p),          M0f = lds2(p + 2),      R0 = lds2(p + 4);
    const float2 L1 = lds2(p + BP),     M1f = lds2(p + BP + 2), R1 = lds2(p + BP + 4);
    float2 L_c = lds2(p + 2 * BP);
    float2 M_c = lds2(p + 2 * BP + 2);
    float2 R_c = lds2(p + 2 * BP + 4);

    float oTa = CORR9(L0.y, M0f.x, M0f.y, L1.y, M1f.x, M1f.y,
                      L_c.y, M_c.x, M_c.y);
    float oTb = CORR9(M0f.y, R0.x, R0.y, M1f.y, R1.x, R1.y,
                      M_c.y, R_c.x, R_c.y);

    float2 M_a = M0f;
    float  lA = L1.y, rA = R1.x;
    float2 M_b = M1f;

#pragma unroll
    for (int k = 0; k < 6; ++k) {
        const float* q = p + (2 * k + 3) * BP;
        const float2 L3 = lds2(q),      M3 = lds2(q + 2),      R3 = lds2(q + 4);
        const float2 L4 = lds2(q + BP), M4 = lds2(q + BP + 2), R4 = lds2(q + BP + 4);

        const float oBa = CORR9(L_c.y, M_c.x, M_c.y, L3.y, M3.x, M3.y,
                                L4.y, M4.x, M4.y);
        const float oBb = CORR9(M_c.y, R_c.x, R_c.y, M3.y, R3.x, R3.y,
                                M4.y, R4.x, R4.y);

        const float lap00 = 4.f * M_b.x - lA - M_b.y - M_a.x - M_c.x;
        const float lap01 = 4.f * M_b.y - M_b.x - rA - M_a.y - M_c.y;
        const float lap10 = 4.f * M_c.x - L_c.y - M_c.y - M_b.x - M3.x;
        const float lap11 = 4.f * M_c.y - M_c.x - R_c.x - M_b.y - M3.y;

        const float r00 = fmaf(alpha, oTa * w4, bs * lap00);
        const float r01 = fmaf(alpha, fmaf(oTa, w5, oTb * w3), bs * lap01);
        const float r10 = fmaf(alpha, fmaf(oTa, w7, oBa * w1), bs * lap10);
        const float r11 = fmaf(alpha,
            fmaf(oTa, w8, fmaf(oTb, w6, fmaf(oBa, w2, oBb * w0))),
            bs * lap11);

        if (K < 5) {
            const int n = (nPack >> (5 * k)) & 31;
            float* ob = out + wio + (2 * k + 1) * BP + 2;   // pixel (2a,2b)
            if (n >= K) {                       // full interior quad (common)
                sts2(ob, r00, r01);
                sts2(ob + BP, r10, r11);
            } else {
                const int m = (mPack >> (5 * k)) & 31;
                if (m >= K) {                   // partial edge quad (rare)
                    const int a = a0 + k;
                    const bool ch = (b <= 73 - K), rh = (a <= 73 - K);
                    ob[0] = r00;
                    if (ch) ob[1] = r01;
                    if (rh) { ob[BP] = r10; if (ch) ob[BP + 1] = r11; }
                }
            }
            fa[4 * k + 0] = fmaf(g, r00, fa[4 * k + 0]);
            fa[4 * k + 1] = fmaf(g, r01, fa[4 * k + 1]);
            fa[4 * k + 2] = fmaf(g, r10, fa[4 * k + 2]);
            fa[4 * k + 3] = fmaf(g, r11, fa[4 * k + 3]);
        } else {
            const int fm = (fmPack >> (4 * k)) & 15;
            if (fm) {
                const int a = a0 + k;
                float* fp = FA + (2 * a - 10) * FAP + (2 * b - 10);
                const float v00 = fmaf(g, r00, fa[4 * k + 0]);
                const float v01 = fmaf(g, r01, fa[4 * k + 1]);
                const float v10 = fmaf(g, r10, fa[4 * k + 2]);
                const float v11 = fmaf(g, r11, fa[4 * k + 3]);
                const bool r0ok = fm & 1, r1ok = fm & 2;
                const bool c0ok = fm & 4, c1ok = fm & 8;
                if (r0ok) {
                    if (c0ok && c1ok) sts2(fp, v00, v01);
                    else { if (c0ok) fp[0] = v00; if (c1ok) fp[1] = v01; }
                }
                if (r1ok) {
                    if (c0ok && c1ok) sts2(fp + FAP, v10, v11);
                    else { if (c0ok) fp[FAP] = v10; if (c1ok) fp[FAP + 1] = v11; }
                }
            }
        }

        // Roll window down 2 rows
        M_a = M_c;
        lA = L3.y; M_b = M3; rA = R3.x;
        L_c = L4; M_c = M4; R_c = R4;
        oTa = oBa; oTb = oBb;
    }
    __syncthreads();
}

// ---------------------------------------------------------------------------
// Mega kernel: fused stage0 + 5 iterations + shrink epilogue. One launch.
// ---------------------------------------------------------------------------
__global__ __launch_bounds__(NT, 1) void mega_kernel(
    const float* __restrict__ STg, const float* __restrict__ dX,
    const float* __restrict__ dY, const float* __restrict__ bX,
    const float* __restrict__ bY, const float* __restrict__ alpha_p,
    const float* __restrict__ beta0_p, const float* __restrict__ beta1_p,
    const float* __restrict__ sigma_p, const float* __restrict__ gamma,
    const float* __restrict__ w9, float* __restrict__ out)
{
    extern __shared__ __align__(16) float sm[];
    float* A  = sm;                 // 149*152
    float* Bb = A + ASIZE;          // 149*152 (+GUARD slack; staging uses it)
    float* FA = Bb;                 // aliases B (dead after iter 4); 129x130

    const int tid = threadIdx.x;
    const int gx0 = blockIdx.x * CORE;
    const int gy0 = blockIdx.y * CORE;

    const float w0 = __ldg(&w9[0]), w1 = __ldg(&w9[1]), w2 = __ldg(&w9[2]);
    const float w3 = __ldg(&w9[3]), w4 = __ldg(&w9[4]), w5 = __ldg(&w9[5]);
    const float w6 = __ldg(&w9[6]), w7 = __ldg(&w9[7]), w8 = __ldg(&w9[8]);
    const float alpha = __ldg(alpha_p);
    const float sigma = __ldg(sigma_p);
    const float bs = __ldg(beta0_p) + sigma;

    const bool interior = (blockIdx.x >= 1) & (blockIdx.x <= gridDim.x - 2) &
                          (blockIdx.y >= 1) & (blockIdx.y <= gridDim.y - 2);

    // ===================== fused stage0: build base0 patch in A ============
    // Pass 1: stage STg patch 151x151 (origin (gy0-11, gx0-11)) into Bb.
    if (interior) {
        const float* src = STg + (gy0 - 11) * WW + (gx0 - 11);
        for (int idx = tid; idx < 151 * 151; idx += NT) {
            const int r = idx / 151, c = idx - r * 151;
            Bb[r * BP + c] = __ldg(src + r * WW + c);
        }
    } else {
        for (int idx = tid; idx < 151 * 151; idx += NT) {
            const int r = idx / 151, c = idx - r * 151;
            Bb[r * BP + c] = __ldg(&STg[((gy0 - 11 + r) & MW) * WW +
                                        ((gx0 - 11 + c) & MW)]);
        }
    }
    __syncthreads();

    // Pass 2: acc = alpha * corr(STg, flip(w))   (kept in registers)
    float acc[NACC];
    {
        int s = 0;
        for (int idx = tid; idx < 149 * 149; idx += NT, ++s) {
            const int r = idx / 149, c = idx - r * 149;
            const float* q = Bb + r * BP + c;
            float conv = fmaf(q[0], w8, q[1] * w7);
            conv = fmaf(q[2], w6, conv);
            conv = fmaf(q[BP], w5, conv);
            conv = fmaf(q[BP + 1], w4, conv);
            conv = fmaf(q[BP + 2], w3, conv);
            conv = fmaf(q[2 * BP], w2, conv);
            conv = fmaf(q[2 * BP + 1], w1, conv);
            conv = fmaf(q[2 * BP + 2], w0, conv);
            acc[s] = alpha * conv;
        }
    }
    __syncthreads();

    // Pass 3: stage u = dX - bX, 149 rows x 150 cols (origin (gy0-10, gx0-11))
    if (interior) {
        const float* ds = dX + (gy0 - 10) * WW + (gx0 - 11);
        const float* bsrc = bX + (gy0 - 10) * WW + (gx0 - 11);
        for (int idx = tid; idx < 149 * 150; idx += NT) {
            const int r = idx / 150, c = idx - r * 150;
            Bb[r * BP + c] = __ldg(ds + r * WW + c) - __ldg(bsrc + r * WW + c);
        }
    } else {
        for (int idx = tid; idx < 149 * 150; idx += NT) {
            const int r = idx / 150, c = idx - r * 150;
            const int gi = (gy0 - 10 + r) & MW, gj = (gx0 - 11 + c) & MW;
            Bb[r * BP + c] = __ldg(&dX[gi * WW + gj]) - __ldg(&bX[gi * WW + gj]);
        }
    }
    __syncthreads();

    // Pass 4: acc += sigma * (u_left - u_center)
    {
        int s = 0;
        for (int idx = tid; idx < 149 * 149; idx += NT, ++s) {
            const int r = idx / 149, c = idx - r * 149;
            acc[s] = fmaf(sigma, Bb[r * BP + c] - Bb[r * BP + c + 1], acc[s]);
        }
    }
    __syncthreads();

    // Pass 5: stage v = dY - bY, 150 rows x 149 cols (origin (gy0-11, gx0-10))
    if (interior) {
        const float* ds = dY + (gy0 - 11) * WW + (gx0 - 10);
        const float* bsrc = bY + (gy0 - 11) * WW + (gx0 - 10);
        for (int idx = tid; idx < 150 * 149; idx += NT) {
            const int r = idx / 149, c = idx - r * 149;
            Bb[r * BP + c] = __ldg(ds + r * WW + c) - __ldg(bsrc + r * WW + c);
        }
    } else {
        for (int idx = tid; idx < 150 * 149; idx += NT) {
            const int r = idx / 149, c = idx - r * 149;
            const int gi = (gy0 - 11 + r) & MW, gj = (gx0 - 10 + c) & MW;
            Bb[r * BP + c] = __ldg(&dY[gi * WW + gj]) - __ldg(&bY[gi * WW + gj]);
        }
    }
    __syncthreads();

    // Pass 6: A = acc + sigma * (v_up - v_center)
    {
        int s = 0;
        for (int idx = tid; idx < 149 * 149; idx += NT, ++s) {
            const int r = idx / 149, c = idx - r * 149;
            A[r * BP + c] =
                fmaf(sigma, Bb[r * BP + c] - Bb[(r + 1) * BP + c], acc[s]);
        }
    }
    __syncthreads();

    // ===================== run precompute ==================================
    int wio, a0, bq, nPack = 0, mPack = 0, fmPack = 0;
    if (tid < NRUN) {
        const int rr = tid / 73;          // 0..12
        bq = tid - rr * 73 + 1;           // 1..73
        a0 = 6 * rr + 1;                  // 1,7,...,73
        wio = (2 * a0 - 1) * BP + (2 * bq - 2);
#pragma unroll
        for (int k = 0; k < 6; ++k) {
            const int a = a0 + k;         // up to 78; a>73 fully gated
            int n = max(0, min(min(a, bq), min(73 - a, 73 - bq)));
            int m = max(0, min(min(a, bq), min(74 - a, 74 - bq)));
            n = min(n, 31); m = min(m, 31);
            const int fm = ((a >= 5 && a <= 69) ? 1 : 0) |
                           ((a >= 5 && a <= 68) ? 2 : 0) |
                           ((bq >= 5 && bq <= 69) ? 4 : 0) |
                           ((bq >= 5 && bq <= 68) ? 8 : 0);
            nPack |= n << (5 * k);
            mPack |= m << (5 * k);
            fmPack |= fm << (4 * k);
        }
    } else {
        wio = 0; a0 = 1; bq = 1;
    }

    // --- f-reg init: fa = gamma[0] * base0 (quad values) -------------------
    float fa[24];
    const float g0 = __ldg(&gamma[0]);
#pragma unroll
    for (int k = 0; k < 6; ++k) {
        const float* pq = A + wio + (2 * k + 1) * BP + 2;
        const float2 u = lds2(pq);
        const float2 v = lds2(pq + BP);
        fa[4 * k + 0] = g0 * u.x;
        fa[4 * k + 1] = g0 * u.y;
        fa[4 * k + 2] = g0 * v.x;
        fa[4 * k + 3] = g0 * v.y;
    }

    iter_step<1>(A, Bb, FA, wio, a0, bq, nPack, mPack, fmPack, fa,
                 w0, w1, w2, w3, w4, w5, w6, w7, w8, alpha, bs, __ldg(&gamma[1]));
    iter_step<2>(Bb, A, FA, wio, a0, bq, nPack, mPack, fmPack, fa,
                 w0, w1, w2, w3, w4, w5, w6, w7, w8, alpha, bs, __ldg(&gamma[2]));
    iter_step<3>(A, Bb, FA, wio, a0, bq, nPack, mPack, fmPack, fa,
                 w0, w1, w2, w3, w4, w5, w6, w7, w8, alpha, bs, __ldg(&gamma[3]));
    iter_step<4>(Bb, A, FA, wio, a0, bq, nPack, mPack, fmPack, fa,
                 w0, w1, w2, w3, w4, w5, w6, w7, w8, alpha, bs, __ldg(&gamma[4]));
    // iter 5 reads A; writes f directly into FA (=Bb, dead since iter-4 sync)
    iter_step<5>(A, Bb, FA, wio, a0, bq, nPack, mPack, fmPack, fa,
                 w0, w1, w2, w3, w4, w5, w6, w7, w8, alpha, bs, __ldg(&gamma[5]));

    // --- shrink / Bregman epilogue: 2 pixels per step ----------------------
    const float thr = __fdividef(__ldg(beta1_p), sigma);
    for (int idx = tid; idx < 128 * 64; idx += NT) {
        const int r = idx >> 6;
        const int cp = idx & 63;
        const float* fr0 = FA + r * FAP + 2 * cp;
        const float2 f0 = lds2(fr0);
        const float fR = fr0[2];
        const float2 f1 = lds2(fr0 + FAP);
        const float dxf0 = f0.y - f0.x, dxf1 = fR - f0.y;
        const float dyf0 = f1.x - f0.x, dyf1 = f1.y - f0.y;
        const int ij = (gy0 + r) * WW + gx0 + 2 * cp;
        const float2 bx = __ldg((const float2*)(bX + ij));
        const float2 by = __ldg((const float2*)(bY + ij));
        const float px0 = dxf0 + bx.x, py0 = dyf0 + by.x;
        const float px1 = dxf1 + bx.y, py1 = dyf1 + by.y;
        const float n0 = sqrtf(fmaf(px0, px0, py0 * py0));
        const float n1 = sqrtf(fmaf(px1, px1, py1 * py1));
        const float sh0 = __fdividef(fmaxf(n0 - thr, 0.f), n0 + 1e-8f);
        const float sh1 = __fdividef(fmaxf(n1 - thr, 0.f), n1 + 1e-8f);
        const float dxn0 = px0 * sh0, dyn0 = py0 * sh0;
        const float dxn1 = px1 * sh1, dyn1 = py1 * sh1;
        *(float2*)(out + ij) = f0;
        *(float2*)(out + NPIX + ij) = make_float2(dxn0, dxn1);
        *(float2*)(out + 2 * NPIX + ij) = make_float2(dyn0, dyn1);
        *(float2*)(out + 3 * NPIX + ij) =
            make_float2(bx.x + dxf0 - dxn0, bx.y + dxf1 - dxn1);
        *(float2*)(out + 4 * NPIX + ij) =
            make_float2(by.x + dyf0 - dyn0, by.y + dyf1 - dyn1);
    }
}

static const int SMEM_BYTES = (2 * ASIZE + GUARD) * 4;

extern "C" void kernel_launch(void* const* d_in, const int* in_sizes, int n_in,
                              void* d_out, int out_size)
{
    const float* STg   = (const float*)d_in[0];
    const float* dX    = (const float*)d_in[1];
    const float* dY    = (const float*)d_in[2];
    const float* bX    = (const float*)d_in[3];
    const float* bY    = (const float*)d_in[4];
    const float* alpha = (const float*)d_in[7];
    const float* beta0 = (const float*)d_in[8];
    const float* beta1 = (const float*)d_in[9];
    const float* sigma = (const float*)d_in[10];
    const float* gamma = (const float*)d_in[11];
    const float* w9    = (const float*)d_in[12];

    float* out = (float*)d_out;

    cudaFuncSetAttribute(mega_kernel,
                         cudaFuncAttributeMaxDynamicSharedMemorySize,
                         SMEM_BYTES);
    dim3 g2(WW / CORE, HH / CORE);
    mega_kernel<<<g2, NT, SMEM_BYTES>>>(STg, dX, dY, bX, bY, alpha, beta0,
                                        beta1, sigma, gamma, w9, out);
}

// round 13
// speedup vs baseline: 1.2325x; 1.2325x over previous
#include <cuda_runtime.h>

#define HH 2048
#define WW 2048
#define MW 2047
#define NPIX (HH * WW)

#define CORE 128
#define B0   149           // patch extent: 128 core + 1 (f diff) + 2*10 halo
#define BP   152           // even pitch
#define FAP  130           // f accumulator pitch (129x129 used)
#define NT   960
#define NRUN 949           // 13 a-runs x 73 b-cols
#define ASIZE (B0 * BP)
#define GUARD 1680         // deepest gated read slack

__device__ float g_base0[NPIX];

__device__ __forceinline__ float2 lds2(const float* p) {
    return *reinterpret_cast<const float2*>(p);
}
__device__ __forceinline__ void sts2(float* p, float x, float y) {
    *reinterpret_cast<float2*>(p) = make_float2(x, y);
}

// Reassociated 9-term correlation: two partial chains + final add.
#define CORR9(x0,x1,x2,x3,x4,x5,x6,x7,x8)                                  \
    (fmaf(x6, w6, fmaf(x4, w4, fmaf(x2, w2, (x0) * w0))) +                 \
     fmaf(x8, w8, fmaf(x7, w7, fmaf(x5, w5, fmaf(x3, w3, (x1) * w1)))))

// ---------------------------------------------------------------------------
// Stage 0: 8 px/thread, float4 x2 fast path, per-THREAD edge test.
// base0 = sigma*(dxT(d_x-b_x)+dyT(d_y-b_y)) + alpha*corr(STg, flip(w))
// ---------------------------------------------------------------------------
__global__ __launch_bounds__(256) void stage0_kernel(
    const float* __restrict__ STg, const float* __restrict__ dX,
    const float* __restrict__ dY, const float* __restrict__ bX,
    const float* __restrict__ bY, const float* __restrict__ alpha_p,
    const float* __restrict__ sigma_p, const float* __restrict__ w9,
    float* __restrict__ base)
{
    const int j = 8 * (blockIdx.x * 32 + threadIdx.x);
    const int i = blockIdx.y * 8 + threadIdx.y;
    const float alpha = __ldg(alpha_p);
    const float sigma = __ldg(sigma_p);
    const int ij = i * WW + j;

    const float w0 = __ldg(&w9[0]), w1 = __ldg(&w9[1]), w2 = __ldg(&w9[2]);
    const float w3 = __ldg(&w9[3]), w4 = __ldg(&w9[4]), w5 = __ldg(&w9[5]);
    const float w6 = __ldg(&w9[6]), w7 = __ldg(&w9[7]), w8 = __ldg(&w9[8]);

    const bool fast = (i > 0) & (i < HH - 1) & (j > 0) & (j + 8 < WW);

    if (fast) {
        const int um = ij - WW, dp = ij + WW;

        const float4 sU0 = __ldg((const float4*)(STg + um));
        const float4 sU1 = __ldg((const float4*)(STg + um + 4));
        const float  sUL = __ldg(&STg[um - 1]), sUR = __ldg(&STg[um + 8]);
        const float4 sM0 = __ldg((const float4*)(STg + ij));
        const float4 sM1 = __ldg((const float4*)(STg + ij + 4));
        const float  sML = __ldg(&STg[ij - 1]), sMR = __ldg(&STg[ij + 8]);
        const float4 sD0 = __ldg((const float4*)(STg + dp));
        const float4 sD1 = __ldg((const float4*)(STg + dp + 4));
        const float  sDL = __ldg(&STg[dp - 1]), sDR = __ldg(&STg[dp + 8]);

        const float up[10] = {sUL, sU0.x, sU0.y, sU0.z, sU0.w,
                              sU1.x, sU1.y, sU1.z, sU1.w, sUR};
        const float md[10] = {sML, sM0.x, sM0.y, sM0.z, sM0.w,
                              sM1.x, sM1.y, sM1.z, sM1.w, sMR};
        const float dn[10] = {sDL, sD0.x, sD0.y, sD0.z, sD0.w,
                              sD1.x, sD1.y, sD1.z, sD1.w, sDR};

        const float4 dx0 = __ldg((const float4*)(dX + ij));
        const float4 dx1 = __ldg((const float4*)(dX + ij + 4));
        const float  dxL = __ldg(&dX[ij - 1]);
        const float4 bx0 = __ldg((const float4*)(bX + ij));
        const float4 bx1 = __ldg((const float4*)(bX + ij + 4));
        const float  bxL = __ldg(&bX[ij - 1]);
        const float4 dyC0 = __ldg((const float4*)(dY + ij));
        const float4 dyC1 = __ldg((const float4*)(dY + ij + 4));
        const float4 dyU0 = __ldg((const float4*)(dY + um));
        const float4 dyU1 = __ldg((const float4*)(dY + um + 4));
        const float4 byC0 = __ldg((const float4*)(bY + ij));
        const float4 byC1 = __ldg((const float4*)(bY + ij + 4));
        const float4 byU0 = __ldg((const float4*)(bY + um));
        const float4 byU1 = __ldg((const float4*)(bY + um + 4));

        const float dxb[9] = {dxL - bxL,
                              dx0.x - bx0.x, dx0.y - bx0.y,
                              dx0.z - bx0.z, dx0.w - bx0.w,
                              dx1.x - bx1.x, dx1.y - bx1.y,
                              dx1.z - bx1.z, dx1.w - bx1.w};
        const float dybC[8] = {dyC0.x - byC0.x, dyC0.y - byC0.y,
                               dyC0.z - byC0.z, dyC0.w - byC0.w,
                               dyC1.x - byC1.x, dyC1.y - byC1.y,
                               dyC1.z - byC1.z, dyC1.w - byC1.w};
        const float dybU[8] = {dyU0.x - byU0.x, dyU0.y - byU0.y,
                               dyU0.z - byU0.z, dyU0.w - byU0.w,
                               dyU1.x - byU1.x, dyU1.y - byU1.y,
                               dyU1.z - byU1.z, dyU1.w - byU1.w};

        float r[8];
#pragma unroll
        for (int t = 0; t < 8; ++t) {
            float conv = fmaf(up[t], w8, up[t + 1] * w7);
            conv = fmaf(up[t + 2], w6, conv);
            conv = fmaf(md[t], w5, conv);
            conv = fmaf(md[t + 1], w4, conv);
            conv = fmaf(md[t + 2], w3, conv);
            conv = fmaf(dn[t], w2, conv);
            conv = fmaf(dn[t + 1], w1, conv);
            conv = fmaf(dn[t + 2], w0, conv);
            const float se = sigma * ((dxb[t] - dxb[t + 1]) +
                                      (dybU[t] - dybC[t]));
            r[t] = fmaf(alpha, conv, se);
        }
        *(float4*)(base + ij) = make_float4(r[0], r[1], r[2], r[3]);
        *(float4*)(base + ij + 4) = make_float4(r[4], r[5], r[6], r[7]);
    } else {
#pragma unroll
        for (int t = 0; t < 8; ++t) {
            const int jj = j + t;
            const int idx = i * WW + jj;
            const int jm = (jj - 1) & MW, im = (i - 1) & MW;
            float dxb_c = __ldg(&dX[idx]) - __ldg(&bX[idx]);
            float dxb_l = __ldg(&dX[i * WW + jm]) - __ldg(&bX[i * WW + jm]);
            float dyb_c = __ldg(&dY[idx]) - __ldg(&bY[idx]);
            float dyb_u = __ldg(&dY[im * WW + jj]) - __ldg(&bY[im * WW + jj]);
            float se = sigma * ((dxb_l - dxb_c) + (dyb_u - dyb_c));
            float conv = 0.f;
#pragma unroll
            for (int p = 0; p < 3; ++p) {
                const int r_ = (i + p - 1) & MW;
#pragma unroll
                for (int q = 0; q < 3; ++q) {
                    const int c = (jj + q - 1) & MW;
                    conv = fmaf(__ldg(&STg[r_ * WW + c]),
                                __ldg(&w9[(2 - p) * 3 + (2 - q)]), conv);
                }
            }
            base[idx] = fmaf(alpha, conv, se);
        }
    }
}

// ---------------------------------------------------------------------------
// One fused _compute iteration: 15-row x 6-col rolling window per vertical
// run of 6 quads. Valid slot range iter K: a,b in [K, 74-K].
// K==1 also initializes fa from the in-window quad values (g0 * base0).
// ---------------------------------------------------------------------------
template <int K>
__device__ __forceinline__ void iter_step(
    const float* __restrict__ in, float* __restrict__ out,
    float* __restrict__ FA,
    int wio, int a0, int b, int nPack, int mPack, int fmPack, float* fa,
    float w0, float w1, float w2, float w3, float w4,
    float w5, float w6, float w7, float w8,
    float alpha, float bs, float g, float g0)
{
    const float* p = in + wio;

    // Prologue: rows 2a0-1, 2a0, 2a0+1, top corners.
    const float2 L0 = lds2(p),          M0f = lds2(p + 2),      R0 = lds2(p + 4);
    const float2 L1 = lds2(p + BP),     M1f = lds2(p + BP + 2), R1 = lds2(p + BP + 4);
    float2 L_c = lds2(p + 2 * BP);
    float2 M_c = lds2(p + 2 * BP + 2);
    float2 R_c = lds2(p + 2 * BP + 4);

    float oTa = CORR9(L0.y, M0f.x, M0f.y, L1.y, M1f.x, M1f.y,
                      L_c.y, M_c.x, M_c.y);
    float oTb = CORR9(M0f.y, R0.x, R0.y, M1f.y, R1.x, R1.y,
                      M_c.y, R_c.x, R_c.y);

    float2 M_a = M0f;
    float  lA = L1.y, rA = R1.x;
    float2 M_b = M1f;

#pragma unroll
    for (int k = 0; k < 6; ++k) {
        const float* q = p + (2 * k + 3) * BP;
        const float2 L3 = lds2(q),      M3 = lds2(q + 2),      R3 = lds2(q + 4);
        const float2 L4 = lds2(q + BP), M4 = lds2(q + BP + 2), R4 = lds2(q + BP + 4);

        const float oBa = CORR9(L_c.y, M_c.x, M_c.y, L3.y, M3.x, M3.y,
                                L4.y, M4.x, M4.y);
        const float oBb = CORR9(M_c.y, R_c.x, R_c.y, M3.y, R3.x, R3.y,
                                M4.y, R4.x, R4.y);

        const float lap00 = 4.f * M_b.x - lA - M_b.y - M_a.x - M_c.x;
        const float lap01 = 4.f * M_b.y - M_b.x - rA - M_a.y - M_c.y;
        const float lap10 = 4.f * M_c.x - L_c.y - M_c.y - M_b.x - M3.x;
        const float lap11 = 4.f * M_c.y - M_c.x - R_c.x - M_b.y - M3.y;

        const float r00 = fmaf(alpha, oTa * w4, bs * lap00);
        const float r01 = fmaf(alpha, fmaf(oTa, w5, oTb * w3), bs * lap01);
        const float r10 = fmaf(alpha, fmaf(oTa, w7, oBa * w1), bs * lap10);
        const float r11 = fmaf(alpha,
            fmaf(oTa, w8, fmaf(oTb, w6, fmaf(oBa, w2, oBb * w0))),
            bs * lap11);

        if (K < 5) {
            const int n = (nPack >> (5 * k)) & 31;
            float* ob = out + wio + (2 * k + 1) * BP + 2;   // pixel (2a,2b)
            if (n >= K) {                       // full interior quad (common)
                sts2(ob, r00, r01);
                sts2(ob + BP, r10, r11);
            } else {
                const int m = (mPack >> (5 * k)) & 31;
                if (m >= K) {                   // partial edge quad (rare)
                    const int a = a0 + k;
                    const bool ch = (b <= 73 - K), rh = (a <= 73 - K);
                    ob[0] = r00;
                    if (ch) ob[1] = r01;
                    if (rh) { ob[BP] = r10; if (ch) ob[BP + 1] = r11; }
                }
            }
            if (K == 1) {
                // fa init folded in: quad values of `in` are M_b (row 2a)
                // and M_c (row 2a+1), cols 2b..2b+1.
                fa[4 * k + 0] = fmaf(g, r00, g0 * M_b.x);
                fa[4 * k + 1] = fmaf(g, r01, g0 * M_b.y);
                fa[4 * k + 2] = fmaf(g, r10, g0 * M_c.x);
                fa[4 * k + 3] = fmaf(g, r11, g0 * M_c.y);
            } else {
                fa[4 * k + 0] = fmaf(g, r00, fa[4 * k + 0]);
                fa[4 * k + 1] = fmaf(g, r01, fa[4 * k + 1]);
                fa[4 * k + 2] = fmaf(g, r10, fa[4 * k + 2]);
                fa[4 * k + 3] = fmaf(g, r11, fa[4 * k + 3]);
            }
        } else {
            const int fm = (fmPack >> (4 * k)) & 15;
            if (fm) {
                const int a = a0 + k;
                float* fp = FA + (2 * a - 10) * FAP + (2 * b - 10);
                const float v00 = fmaf(g, r00, fa[4 * k + 0]);
                const float v01 = fmaf(g, r01, fa[4 * k + 1]);
                const float v10 = fmaf(g, r10, fa[4 * k + 2]);
                const float v11 = fmaf(g, r11, fa[4 * k + 3]);
                const bool r0ok = fm & 1, r1ok = fm & 2;
                const bool c0ok = fm & 4, c1ok = fm & 8;
                if (r0ok) {
                    if (c0ok && c1ok) sts2(fp, v00, v01);
                    else { if (c0ok) fp[0] = v00; if (c1ok) fp[1] = v01; }
                }
                if (r1ok) {
                    if (c0ok && c1ok) sts2(fp + FAP, v10, v11);
                    else { if (c0ok) fp[FAP] = v10; if (c1ok) fp[FAP + 1] = v11; }
                }
            }
        }

        // Roll window down 2 rows
        M_a = M_c;
        lA = L3.y; M_b = M3; rA = R3.x;
        L_c = L4; M_c = M4; R_c = R4;
        oTa = oBa; oTb = oBb;
    }
    __syncthreads();
}

// ---------------------------------------------------------------------------
// Mega kernel: 5 fused iterations + shrink epilogue, 128x128 core per block.
// ---------------------------------------------------------------------------
__global__ __launch_bounds__(NT, 1) void mega_kernel(
    const float* __restrict__ base0, const float* __restrict__ bX,
    const float* __restrict__ bY, const float* __restrict__ alpha_p,
    const float* __restrict__ beta0_p, const float* __restrict__ beta1_p,
    const float* __restrict__ sigma_p, const float* __restrict__ gamma,
    const float* __restrict__ w9, float* __restrict__ out)
{
    extern __shared__ __align__(16) float sm[];
    float* A  = sm;                 // 149*152
    float* B  = A + ASIZE;          // 149*152 (+GUARD slack for gated reads)
    float* FA = B;                  // aliases B (dead after iter 4); 129x130

    const int tid = threadIdx.x;
    const int gx0 = blockIdx.x * CORE;
    const int gy0 = blockIdx.y * CORE;

    const float w0 = __ldg(&w9[0]), w1 = __ldg(&w9[1]), w2 = __ldg(&w9[2]);
    const float w3 = __ldg(&w9[3]), w4 = __ldg(&w9[4]), w5 = __ldg(&w9[5]);
    const float w6 = __ldg(&w9[6]), w7 = __ldg(&w9[7]), w8 = __ldg(&w9[8]);
    const float alpha = __ldg(alpha_p);
    const float bs = __ldg(beta0_p) + __ldg(sigma_p);

    // --- run precompute: vertical run of 6 quads (a0..a0+5, b) -------------
    int wio, a0, bq, nPack = 0, mPack = 0, fmPack = 0;
    if (tid < NRUN) {
        const int rr = tid / 73;          // 0..12
        bq = tid - rr * 73 + 1;           // 1..73
        a0 = 6 * rr + 1;                  // 1,7,...,73
        wio = (2 * a0 - 1) * BP + (2 * bq - 2);
#pragma unroll
        for (int k = 0; k < 6; ++k) {
            const int a = a0 + k;         // up to 78; a>73 fully gated
            int n = max(0, min(min(a, bq), min(73 - a, 73 - bq)));
            int m = max(0, min(min(a, bq), min(74 - a, 74 - bq)));
            n = min(n, 31); m = min(m, 31);
            const int fm = ((a >= 5 && a <= 69) ? 1 : 0) |
                           ((a >= 5 && a <= 68) ? 2 : 0) |
                           ((bq >= 5 && bq <= 69) ? 4 : 0) |
                           ((bq >= 5 && bq <= 68) ? 8 : 0);
            nPack |= n << (5 * k);
            mPack |= m << (5 * k);
            fmPack |= fm << (4 * k);
        }
    } else {
        wio = 0; a0 = 1; bq = 1;
    }

    // --- load 149x149 base0 patch -----------------------------------------
    const bool interior = (blockIdx.x >= 1) & (blockIdx.x <= gridDim.x - 2) &
                          (blockIdx.y >= 1) & (blockIdx.y <= gridDim.y - 2);
    if (interior) {
        const float* src = base0 + (gy0 - 10) * WW + (gx0 - 10);
        for (int idx = tid; idx < B0 * 75; idx += NT) {
            const int r = idx / 75;
            const int c2 = idx - r * 75;
            const float2 v = __ldg((const float2*)(src + r * WW + 2 * c2));
            *(float2*)(A + r * BP + 2 * c2) = v;
        }
    } else {
        for (int idx = tid; idx < B0 * B0; idx += NT) {
            const int r = idx / B0;
            const int c = idx - r * B0;
            A[r * BP + c] = __ldg(&base0[((gy0 - 10 + r) & MW) * WW +
                                         ((gx0 - 10 + c) & MW)]);
        }
    }
    __syncthreads();

    float fa[24];
    const float g0 = __ldg(&gamma[0]);

    iter_step<1>(A, B, FA, wio, a0, bq, nPack, mPack, fmPack, fa,
                 w0, w1, w2, w3, w4, w5, w6, w7, w8, alpha, bs,
                 __ldg(&gamma[1]), g0);
    iter_step<2>(B, A, FA, wio, a0, bq, nPack, mPack, fmPack, fa,
                 w0, w1, w2, w3, w4, w5, w6, w7, w8, alpha, bs,
                 __ldg(&gamma[2]), g0);
    iter_step<3>(A, B, FA, wio, a0, bq, nPack, mPack, fmPack, fa,
                 w0, w1, w2, w3, w4, w5, w6, w7, w8, alpha, bs,
                 __ldg(&gamma[3]), g0);
    iter_step<4>(B, A, FA, wio, a0, bq, nPack, mPack, fmPack, fa,
                 w0, w1, w2, w3, w4, w5, w6, w7, w8, alpha, bs,
                 __ldg(&gamma[4]), g0);
    // iter 5 reads A; writes f directly into FA (=B, dead since iter-4 sync)
    iter_step<5>(A, B, FA, wio, a0, bq, nPack, mPack, fmPack, fa,
                 w0, w1, w2, w3, w4, w5, w6, w7, w8, alpha, bs,
                 __ldg(&gamma[5]), g0);

    // --- shrink / Bregman epilogue: 2 pixels per step ----------------------
    const float thr = __fdividef(__ldg(beta1_p), __ldg(sigma_p));
    for (int idx = tid; idx < 128 * 64; idx += NT) {
        const int r = idx >> 6;
        const int cp = idx & 63;
        const float* fr0 = FA + r * FAP + 2 * cp;
        const float2 f0 = lds2(fr0);
        const float fR = fr0[2];
        const float2 f1 = lds2(fr0 + FAP);
        const float dxf0 = f0.y - f0.x, dxf1 = fR - f0.y;
        const float dyf0 = f1.x - f0.x, dyf1 = f1.y - f0.y;
        const int ij = (gy0 + r) * WW + gx0 + 2 * cp;
        const float2 bx = __ldg((const float2*)(bX + ij));
        const float2 by = __ldg((const float2*)(bY + ij));
        const float px0 = dxf0 + bx.x, py0 = dyf0 + by.x;
        const float px1 = dxf1 + bx.y, py1 = dyf1 + by.y;
        const float n0 = sqrtf(fmaf(px0, px0, py0 * py0));
        const float n1 = sqrtf(fmaf(px1, px1, py1 * py1));
        const float sh0 = __fdividef(fmaxf(n0 - thr, 0.f), n0 + 1e-8f);
        const float sh1 = __fdividef(fmaxf(n1 - thr, 0.f), n1 + 1e-8f);
        const float dxn0 = px0 * sh0, dyn0 = py0 * sh0;
        const float dxn1 = px1 * sh1, dyn1 = py1 * sh1;
        *(float2*)(out + ij) = f0;
        *(float2*)(out + NPIX + ij) = make_float2(dxn0, dxn1);
        *(float2*)(out + 2 * NPIX + ij) = make_float2(dyn0, dyn1);
        *(float2*)(out + 3 * NPIX + ij) =
            make_float2(bx.x + dxf0 - dxn0, bx.y + dxf1 - dxn1);
        *(float2*)(out + 4 * NPIX + ij) =
            make_float2(by.x + dyf0 - dyn0, by.y + dyf1 - dyn1);
    }
}

static const int SMEM_BYTES = (2 * ASIZE + GUARD) * 4;

extern "C" void kernel_launch(void* const* d_in, const int* in_sizes, int n_in,
                              void* d_out, int out_size)
{
    const float* STg   = (const float*)d_in[0];
    const float* dX    = (const float*)d_in[1];
    const float* dY    = (const float*)d_in[2];
    const float* bX    = (const float*)d_in[3];
    const float* bY    = (const float*)d_in[4];
    const float* alpha = (const float*)d_in[7];
    const float* beta0 = (const float*)d_in[8];
    const float* beta1 = (const float*)d_in[9];
    const float* sigma = (const float*)d_in[10];
    const float* gamma = (const float*)d_in[11];
    const float* w9    = (const float*)d_in[12];

    float* out = (float*)d_out;

    float* pB0;
    cudaGetSymbolAddress((void**)&pB0, g_base0);

    dim3 b1(32, 8), g1(WW / 256, HH / 8);
    stage0_kernel<<<g1, b1>>>(STg, dX, dY, bX, bY, alpha, sigma, w9, pB0);

    cudaFuncSetAttribute(mega_kernel,
                         cudaFuncAttributeMaxDynamicSharedMemorySize,
                         SMEM_BYTES);
    dim3 g2(WW / CORE, HH / CORE);
    mega_kernel<<<g2, NT, SMEM_BYTES>>>(pB0, bX, bY, alpha, beta0, beta1,
                                        sigma, gamma, w9, out);
}

// round 14
// speedup vs baseline: 1.2931x; 1.0492x over previous
#include <cuda_runtime.h>

#define HH 2048
#define WW 2048
#define MW 2047
#define NPIX (HH * WW)

#define CORE 128
#define B0   149           // patch extent: 128 core + 1 (f diff) + 2*10 halo
#define BP   152           // even pitch
#define FAP  130           // f accumulator pitch (129x129 used)
#define NT   1024
#define NRUN 949           // 13 a-runs x 73 b-cols
#define ASIZE (B0 * BP)
#define GUARD 1680         // deepest gated read slack

__device__ float g_base0[NPIX];

__device__ __forceinline__ float2 lds2(const float* p) {
    return *reinterpret_cast<const float2*>(p);
}
__device__ __forceinline__ void sts2(float* p, float x, float y) {
    *reinterpret_cast<float2*>(p) = make_float2(x, y);
}

// Reassociated 9-term correlation: two partial chains + final add.
#define CORR9(x0,x1,x2,x3,x4,x5,x6,x7,x8)                                  \
    (fmaf(x6, w6, fmaf(x4, w4, fmaf(x2, w2, (x0) * w0))) +                 \
     fmaf(x8, w8, fmaf(x7, w7, fmaf(x5, w5, fmaf(x3, w3, (x1) * w1)))))

// ---------------------------------------------------------------------------
// Stage 0: 4 px/thread, float4 interior path (R9-proven fastest variant).
// base0 = sigma*(dxT(d_x-b_x)+dyT(d_y-b_y)) + alpha*corr(STg, flip(w))
// ---------------------------------------------------------------------------
__global__ __launch_bounds__(256) void stage0_kernel(
    const float* __restrict__ STg, const float* __restrict__ dX,
    const float* __restrict__ dY, const float* __restrict__ bX,
    const float* __restrict__ bY, const float* __restrict__ alpha_p,
    const float* __restrict__ sigma_p, const float* __restrict__ w9,
    float* __restrict__ base)
{
    const int j = 4 * (blockIdx.x * 32 + threadIdx.x);
    const int i = blockIdx.y * 8 + threadIdx.y;
    const float alpha = __ldg(alpha_p);
    const float sigma = __ldg(sigma_p);
    const int ij = i * WW + j;

    const bool border = (blockIdx.x == 0) | (blockIdx.x == gridDim.x - 1) |
                        (blockIdx.y == 0) | (blockIdx.y == gridDim.y - 1);

    if (!border) {
        const float w0 = __ldg(&w9[0]), w1 = __ldg(&w9[1]), w2 = __ldg(&w9[2]);
        const float w3 = __ldg(&w9[3]), w4 = __ldg(&w9[4]), w5 = __ldg(&w9[5]);
        const float w6 = __ldg(&w9[6]), w7 = __ldg(&w9[7]), w8 = __ldg(&w9[8]);
        const int um = ij - WW, dp = ij + WW;

        const float4 sC = __ldg((const float4*)(STg + ij));
        const float  sL = __ldg(&STg[ij - 1]),  sR = __ldg(&STg[ij + 4]);
        const float4 sU = __ldg((const float4*)(STg + um));
        const float  sUL = __ldg(&STg[um - 1]), sUR = __ldg(&STg[um + 4]);
        const float4 sD = __ldg((const float4*)(STg + dp));
        const float  sDL = __ldg(&STg[dp - 1]), sDR = __ldg(&STg[dp + 4]);

        const float up[6]  = {sUL, sU.x, sU.y, sU.z, sU.w, sUR};
        const float md[6]  = {sL,  sC.x, sC.y, sC.z, sC.w, sR};
        const float dn[6]  = {sDL, sD.x, sD.y, sD.z, sD.w, sDR};

        const float4 dxC = __ldg((const float4*)(dX + ij));
        const float  dxL = __ldg(&dX[ij - 1]);
        const float4 bxC = __ldg((const float4*)(bX + ij));
        const float  bxL = __ldg(&bX[ij - 1]);
        const float4 dyC = __ldg((const float4*)(dY + ij));
        const float4 dyU = __ldg((const float4*)(dY + um));
        const float4 byC = __ldg((const float4*)(bY + ij));
        const float4 byU = __ldg((const float4*)(bY + um));

        const float dxb[5] = {dxL - bxL, dxC.x - bxC.x, dxC.y - bxC.y,
                              dxC.z - bxC.z, dxC.w - bxC.w};
        const float dybC[4] = {dyC.x - byC.x, dyC.y - byC.y,
                               dyC.z - byC.z, dyC.w - byC.w};
        const float dybU[4] = {dyU.x - byU.x, dyU.y - byU.y,
                               dyU.z - byU.z, dyU.w - byU.w};

        float4 r;
        float* rp = &r.x;
#pragma unroll
        for (int t = 0; t < 4; ++t) {
            float conv = fmaf(up[t], w8, up[t + 1] * w7);
            conv = fmaf(up[t + 2], w6, conv);
            conv = fmaf(md[t], w5, conv);
            conv = fmaf(md[t + 1], w4, conv);
            conv = fmaf(md[t + 2], w3, conv);
            conv = fmaf(dn[t], w2, conv);
            conv = fmaf(dn[t + 1], w1, conv);
            conv = fmaf(dn[t + 2], w0, conv);
            const float se = sigma * ((dxb[t] - dxb[t + 1]) +
                                      (dybU[t] - dybC[t]));
            rp[t] = fmaf(alpha, conv, se);
        }
        *(float4*)(base + ij) = r;
    } else {
#pragma unroll
        for (int t = 0; t < 4; ++t) {
            const int jj = j + t;
            const int idx = i * WW + jj;
            const int jm = (jj - 1) & MW, im = (i - 1) & MW;
            float dxb_c = __ldg(&dX[idx]) - __ldg(&bX[idx]);
            float dxb_l = __ldg(&dX[i * WW + jm]) - __ldg(&bX[i * WW + jm]);
            float dyb_c = __ldg(&dY[idx]) - __ldg(&bY[idx]);
            float dyb_u = __ldg(&dY[im * WW + jj]) - __ldg(&bY[im * WW + jj]);
            float se = sigma * ((dxb_l - dxb_c) + (dyb_u - dyb_c));
            float conv = 0.f;
#pragma unroll
            for (int p = 0; p < 3; ++p) {
                const int r_ = (i + p - 1) & MW;
#pragma unroll
                for (int q = 0; q < 3; ++q) {
                    const int c = (jj + q - 1) & MW;
                    conv = fmaf(__ldg(&STg[r_ * WW + c]),
                                __ldg(&w9[(2 - p) * 3 + (2 - q)]), conv);
                }
            }
            base[idx] = fmaf(alpha, conv, se);
        }
    }
}

// ---------------------------------------------------------------------------
// One fused _compute iteration: 15-row x 6-col rolling window per vertical
// run of 6 quads. Valid slot range iter K: a,b in [K, 74-K].
// K==1 also initializes fa from the in-window quad values (g0 * base0).
// ---------------------------------------------------------------------------
template <int K>
__device__ __forceinline__ void iter_step(
    const float* __restrict__ in, float* __restrict__ out,
    float* __restrict__ FA,
    int wio, int a0, int b, int nPack, int mPack, int fmPack, float* fa,
    float w0, float w1, float w2, float w3, float w4,
    float w5, float w6, float w7, float w8,
    float alpha, float bs, float g, float g0)
{
    const float* p = in + wio;

    // Prologue: rows 2a0-1, 2a0, 2a0+1, top corners.
    const float2 L0 = lds2(p),          M0f = lds2(p + 2),      R0 = lds2(p + 4);
    const float2 L1 = lds2(p + BP),     M1f = lds2(p + BP + 2), R1 = lds2(p + BP + 4);
    float2 L_c = lds2(p + 2 * BP);
    float2 M_c = lds2(p + 2 * BP + 2);
    float2 R_c = lds2(p + 2 * BP + 4);

    float oTa = CORR9(L0.y, M0f.x, M0f.y, L1.y, M1f.x, M1f.y,
                      L_c.y, M_c.x, M_c.y);
    float oTb = CORR9(M0f.y, R0.x, R0.y, M1f.y, R1.x, R1.y,
                      M_c.y, R_c.x, R_c.y);

    float2 M_a = M0f;
    float  lA = L1.y, rA = R1.x;
    float2 M_b = M1f;

#pragma unroll
    for (int k = 0; k < 6; ++k) {
        const float* q = p + (2 * k + 3) * BP;
        const float2 L3 = lds2(q),      M3 = lds2(q + 2),      R3 = lds2(q + 4);
        const float2 L4 = lds2(q + BP), M4 = lds2(q + BP + 2), R4 = lds2(q + BP + 4);

        const float oBa = CORR9(L_c.y, M_c.x, M_c.y, L3.y, M3.x, M3.y,
                                L4.y, M4.x, M4.y);
        const float oBb = CORR9(M_c.y, R_c.x, R_c.y, M3.y, R3.x, R3.y,
                                M4.y, R4.x, R4.y);

        const float lap00 = 4.f * M_b.x - lA - M_b.y - M_a.x - M_c.x;
        const float lap01 = 4.f * M_b.y - M_b.x - rA - M_a.y - M_c.y;
        const float lap10 = 4.f * M_c.x - L_c.y - M_c.y - M_b.x - M3.x;
        const float lap11 = 4.f * M_c.y - M_c.x - R_c.x - M_b.y - M3.y;

        const float r00 = fmaf(alpha, oTa * w4, bs * lap00);
        const float r01 = fmaf(alpha, fmaf(oTa, w5, oTb * w3), bs * lap01);
        const float r10 = fmaf(alpha, fmaf(oTa, w7, oBa * w1), bs * lap10);
        const float r11 = fmaf(alpha,
            fmaf(oTa, w8, fmaf(oTb, w6, fmaf(oBa, w2, oBb * w0))),
            bs * lap11);

        if (K < 5) {
            const int n = (nPack >> (5 * k)) & 31;
            float* ob = out + wio + (2 * k + 1) * BP + 2;   // pixel (2a,2b)
            if (n >= K) {                       // full interior quad (common)
                sts2(ob, r00, r01);
                sts2(ob + BP, r10, r11);
            } else {
                const int m = (mPack >> (5 * k)) & 31;
                if (m >= K) {                   // partial edge quad (rare)
                    const int a = a0 + k;
                    const bool ch = (b <= 73 - K), rh = (a <= 73 - K);
                    ob[0] = r00;
                    if (ch) ob[1] = r01;
                    if (rh) { ob[BP] = r10; if (ch) ob[BP + 1] = r11; }
                }
            }
            if (K == 1) {
                // fa init folded in: quad values of `in` are M_b (row 2a)
                // and M_c (row 2a+1), cols 2b..2b+1.
                fa[4 * k + 0] = fmaf(g, r00, g0 * M_b.x);
                fa[4 * k + 1] = fmaf(g, r01, g0 * M_b.y);
                fa[4 * k + 2] = fmaf(g, r10, g0 * M_c.x);
                fa[4 * k + 3] = fmaf(g, r11, g0 * M_c.y);
            } else {
                fa[4 * k + 0] = fmaf(g, r00, fa[4 * k + 0]);
                fa[4 * k + 1] = fmaf(g, r01, fa[4 * k + 1]);
                fa[4 * k + 2] = fmaf(g, r10, fa[4 * k + 2]);
                fa[4 * k + 3] = fmaf(g, r11, fa[4 * k + 3]);
            }
        } else {
            const int fm = (fmPack >> (4 * k)) & 15;
            if (fm) {
                const int a = a0 + k;
                float* fp = FA + (2 * a - 10) * FAP + (2 * b - 10);
                const float v00 = fmaf(g, r00, fa[4 * k + 0]);
                const float v01 = fmaf(g, r01, fa[4 * k + 1]);
                const float v10 = fmaf(g, r10, fa[4 * k + 2]);
                const float v11 = fmaf(g, r11, fa[4 * k + 3]);
                const bool r0ok = fm & 1, r1ok = fm & 2;
                const bool c0ok = fm & 4, c1ok = fm & 8;
                if (r0ok) {
                    if (c0ok && c1ok) sts2(fp, v00, v01);
                    else { if (c0ok) fp[0] = v00; if (c1ok) fp[1] = v01; }
                }
                if (r1ok) {
                    if (c0ok && c1ok) sts2(fp + FAP, v10, v11);
                    else { if (c0ok) fp[FAP] = v10; if (c1ok) fp[FAP + 1] = v11; }
                }
            }
        }

        // Roll window down 2 rows
        M_a = M_c;
        lA = L3.y; M_b = M3; rA = R3.x;
        L_c = L4; M_c = M4; R_c = R4;
        oTa = oBa; oTb = oBb;
    }
    __syncthreads();
}

// ---------------------------------------------------------------------------
// Mega kernel: 5 fused iterations + shrink epilogue, 128x128 core per block.
// ---------------------------------------------------------------------------
__global__ __launch_bounds__(NT, 1) void mega_kernel(
    const float* __restrict__ base0, const float* __restrict__ bX,
    const float* __restrict__ bY, const float* __restrict__ alpha_p,
    const float* __restrict__ beta0_p, const float* __restrict__ beta1_p,
    const float* __restrict__ sigma_p, const float* __restrict__ gamma,
    const float* __restrict__ w9, float* __restrict__ out)
{
    extern __shared__ __align__(16) float sm[];
    float* A  = sm;                 // 149*152
    float* B  = A + ASIZE;          // 149*152 (+GUARD slack for gated reads)
    float* FA = B;                  // aliases B (dead after iter 4); 129x130

    const int tid = threadIdx.x;
    const int gx0 = blockIdx.x * CORE;
    const int gy0 = blockIdx.y * CORE;

    const float w0 = __ldg(&w9[0]), w1 = __ldg(&w9[1]), w2 = __ldg(&w9[2]);
    const float w3 = __ldg(&w9[3]), w4 = __ldg(&w9[4]), w5 = __ldg(&w9[5]);
    const float w6 = __ldg(&w9[6]), w7 = __ldg(&w9[7]), w8 = __ldg(&w9[8]);
    const float alpha = __ldg(alpha_p);
    const float bs = __ldg(beta0_p) + __ldg(sigma_p);

    // --- run precompute: vertical run of 6 quads (a0..a0+5, b) -------------
    int wio, a0, bq, nPack = 0, mPack = 0, fmPack = 0;
    if (tid < NRUN) {
        const int rr = tid / 73;          // 0..12
        bq = tid - rr * 73 + 1;           // 1..73
        a0 = 6 * rr + 1;                  // 1,7,...,73
        wio = (2 * a0 - 1) * BP + (2 * bq - 2);
#pragma unroll
        for (int k = 0; k < 6; ++k) {
            const int a = a0 + k;         // up to 78; a>73 fully gated
            int n = max(0, min(min(a, bq), min(73 - a, 73 - bq)));
            int m = max(0, min(min(a, bq), min(74 - a, 74 - bq)));
            n = min(n, 31); m = min(m, 31);
            const int fm = ((a >= 5 && a <= 69) ? 1 : 0) |
                           ((a >= 5 && a <= 68) ? 2 : 0) |
                           ((bq >= 5 && bq <= 69) ? 4 : 0) |
                           ((bq >= 5 && bq <= 68) ? 8 : 0);
            nPack |= n << (5 * k);
            mPack |= m << (5 * k);
            fmPack |= fm << (4 * k);
        }
    } else {
        wio = 0; a0 = 1; bq = 1;
    }

    // --- load 149x149 base0 patch -----------------------------------------
    const bool interior = (blockIdx.x >= 1) & (blockIdx.x <= gridDim.x - 2) &
                          (blockIdx.y >= 1) & (blockIdx.y <= gridDim.y - 2);
    if (interior) {
        const float* src = base0 + (gy0 - 10) * WW + (gx0 - 10);
        for (int idx = tid; idx < B0 * 75; idx += NT) {
            const int r = idx / 75;
            const int c2 = idx - r * 75;
            const float2 v = __ldg((const float2*)(src + r * WW + 2 * c2));
            *(float2*)(A + r * BP + 2 * c2) = v;
        }
    } else {
        for (int idx = tid; idx < B0 * B0; idx += NT) {
            const int r = idx / B0;
            const int c = idx - r * B0;
            A[r * BP + c] = __ldg(&base0[((gy0 - 10 + r) & MW) * WW +
                                         ((gx0 - 10 + c) & MW)]);
        }
    }
    __syncthreads();

    float fa[24];
    const float g0 = __ldg(&gamma[0]);

    iter_step<1>(A, B, FA, wio, a0, bq, nPack, mPack, fmPack, fa,
                 w0, w1, w2, w3, w4, w5, w6, w7, w8, alpha, bs,
                 __ldg(&gamma[1]), g0);
    iter_step<2>(B, A, FA, wio, a0, bq, nPack, mPack, fmPack, fa,
                 w0, w1, w2, w3, w4, w5, w6, w7, w8, alpha, bs,
                 __ldg(&gamma[2]), g0);
    iter_step<3>(A, B, FA, wio, a0, bq, nPack, mPack, fmPack, fa,
                 w0, w1, w2, w3, w4, w5, w6, w7, w8, alpha, bs,
                 __ldg(&gamma[3]), g0);
    iter_step<4>(B, A, FA, wio, a0, bq, nPack, mPack, fmPack, fa,
                 w0, w1, w2, w3, w4, w5, w6, w7, w8, alpha, bs,
                 __ldg(&gamma[4]), g0);
    // iter 5 reads A; writes f directly into FA (=B, dead since iter-4 sync)
    iter_step<5>(A, B, FA, wio, a0, bq, nPack, mPack, fmPack, fa,
                 w0, w1, w2, w3, w4, w5, w6, w7, w8, alpha, bs,
                 __ldg(&gamma[5]), g0);

    // --- shrink / Bregman epilogue: 2 pixels per step ----------------------
    const float thr = __fdividef(__ldg(beta1_p), __ldg(sigma_p));
    for (int idx = tid; idx < 128 * 64; idx += NT) {
        const int r = idx >> 6;
        const int cp = idx & 63;
        const float* fr0 = FA + r * FAP + 2 * cp;
        const float2 f0 = lds2(fr0);
        const float fR = fr0[2];
        const float2 f1 = lds2(fr0 + FAP);
        const float dxf0 = f0.y - f0.x, dxf1 = fR - f0.y;
        const float dyf0 = f1.x - f0.x, dyf1 = f1.y - f0.y;
        const int ij = (gy0 + r) * WW + gx0 + 2 * cp;
        const float2 bx = __ldg((const float2*)(bX + ij));
        const float2 by = __ldg((const float2*)(bY + ij));
        const float px0 = dxf0 + bx.x, py0 = dyf0 + by.x;
        const float px1 = dxf1 + bx.y, py1 = dyf1 + by.y;
        const float n0 = sqrtf(fmaf(px0, px0, py0 * py0));
        const float n1 = sqrtf(fmaf(px1, px1, py1 * py1));
        const float sh0 = __fdividef(fmaxf(n0 - thr, 0.f), n0 + 1e-8f);
        const float sh1 = __fdividef(fmaxf(n1 - thr, 0.f), n1 + 1e-8f);
        const float dxn0 = px0 * sh0, dyn0 = py0 * sh0;
        const float dxn1 = px1 * sh1, dyn1 = py1 * sh1;
        *(float2*)(out + ij) = f0;
        *(float2*)(out + NPIX + ij) = make_float2(dxn0, dxn1);
        *(float2*)(out + 2 * NPIX + ij) = make_float2(dyn0, dyn1);
        *(float2*)(out + 3 * NPIX + ij) =
            make_float2(bx.x + dxf0 - dxn0, bx.y + dxf1 - dxn1);
        *(float2*)(out + 4 * NPIX + ij) =
            make_float2(by.x + dyf0 - dyn0, by.y + dyf1 - dyn1);
    }
}

static const int SMEM_BYTES = (2 * ASIZE + GUARD) * 4;

extern "C" void kernel_launch(void* const* d_in, const int* in_sizes, int n_in,
                              void* d_out, int out_size)
{
    const float* STg   = (const float*)d_in[0];
    const float* dX    = (const float*)d_in[1];
    const float* dY    = (const float*)d_in[2];
    const float* bX    = (const float*)d_in[3];
    const float* bY    = (const float*)d_in[4];
    const float* alpha = (const float*)d_in[7];
    const float* beta0 = (const float*)d_in[8];
    const float* beta1 = (const float*)d_in[9];
    const float* sigma = (const float*)d_in[10];
    const float* gamma = (const float*)d_in[11];
    const float* w9    = (const float*)d_in[12];

    float* out = (float*)d_out;

    float* pB0;
    cudaGetSymbolAddress((void**)&pB0, g_base0);

    dim3 b1(32, 8), g1(WW / 128, HH / 8);
    stage0_kernel<<<g1, b1>>>(STg, dX, dY, bX, bY, alpha, sigma, w9, pB0);

    cudaFuncSetAttribute(mega_kernel,
                         cudaFuncAttributeMaxDynamicSharedMemorySize,
                         SMEM_BYTES);
    dim3 g2(WW / CORE, HH / CORE);
    mega_kernel<<<g2, NT, SMEM_BYTES>>>(pB0, bX, bY, alpha, beta0, beta1,
                                        sigma, gamma, w9, out);
}

// round 15
// speedup vs baseline: 1.3594x; 1.0513x over previous
#include <cuda_runtime.h>

#define HH 2048
#define WW 2048
#define MW 2047
#define NPIX (HH * WW)

#define CORE 128
#define B0   149           // patch rows: 128 core + 1 (f diff) + 2*10 halo
#define BP   152           // patch pitch; cols hold global gx0-12 .. gx0+139
#define FAP  132           // f accumulator pitch (16B-aligned rows)
#define NT   1024
#define NRUN 949           // 13 a-runs x 73 b-cols
#define ASIZE (B0 * BP)
#define GUARD 1680         // max gated read = 1672 floats past B

__device__ float g_base0[NPIX];

__device__ __forceinline__ float2 lds2(const float* p) {
    return *reinterpret_cast<const float2*>(p);
}
__device__ __forceinline__ void sts2(float* p, float x, float y) {
    *reinterpret_cast<float2*>(p) = make_float2(x, y);
}

// Reassociated 9-term correlation: two partial chains + final add.
#define CORR9(x0,x1,x2,x3,x4,x5,x6,x7,x8)                                  \
    (fmaf(x6, w6, fmaf(x4, w4, fmaf(x2, w2, (x0) * w0))) +                 \
     fmaf(x8, w8, fmaf(x7, w7, fmaf(x5, w5, fmaf(x3, w3, (x1) * w1)))))

// ---------------------------------------------------------------------------
// Stage 0: 4 px/thread, float4 interior path (R9-proven fastest variant).
// base0 = sigma*(dxT(d_x-b_x)+dyT(d_y-b_y)) + alpha*corr(STg, flip(w))
// ---------------------------------------------------------------------------
__global__ __launch_bounds__(256) void stage0_kernel(
    const float* __restrict__ STg, const float* __restrict__ dX,
    const float* __restrict__ dY, const float* __restrict__ bX,
    const float* __restrict__ bY, const float* __restrict__ alpha_p,
    const float* __restrict__ sigma_p, const float* __restrict__ w9,
    float* __restrict__ base)
{
    const int j = 4 * (blockIdx.x * 32 + threadIdx.x);
    const int i = blockIdx.y * 8 + threadIdx.y;
    const float alpha = __ldg(alpha_p);
    const float sigma = __ldg(sigma_p);
    const int ij = i * WW + j;

    const bool border = (blockIdx.x == 0) | (blockIdx.x == gridDim.x - 1) |
                        (blockIdx.y == 0) | (blockIdx.y == gridDim.y - 1);

    if (!border) {
        const float w0 = __ldg(&w9[0]), w1 = __ldg(&w9[1]), w2 = __ldg(&w9[2]);
        const float w3 = __ldg(&w9[3]), w4 = __ldg(&w9[4]), w5 = __ldg(&w9[5]);
        const float w6 = __ldg(&w9[6]), w7 = __ldg(&w9[7]), w8 = __ldg(&w9[8]);
        const int um = ij - WW, dp = ij + WW;

        const float4 sC = __ldg((const float4*)(STg + ij));
        const float  sL = __ldg(&STg[ij - 1]),  sR = __ldg(&STg[ij + 4]);
        const float4 sU = __ldg((const float4*)(STg + um));
        const float  sUL = __ldg(&STg[um - 1]), sUR = __ldg(&STg[um + 4]);
        const float4 sD = __ldg((const float4*)(STg + dp));
        const float  sDL = __ldg(&STg[dp - 1]), sDR = __ldg(&STg[dp + 4]);

        const float up[6]  = {sUL, sU.x, sU.y, sU.z, sU.w, sUR};
        const float md[6]  = {sL,  sC.x, sC.y, sC.z, sC.w, sR};
        const float dn[6]  = {sDL, sD.x, sD.y, sD.z, sD.w, sDR};

        const float4 dxC = __ldg((const float4*)(dX + ij));
        const float  dxL = __ldg(&dX[ij - 1]);
        const float4 bxC = __ldg((const float4*)(bX + ij));
        const float  bxL = __ldg(&bX[ij - 1]);
        const float4 dyC = __ldg((const float4*)(dY + ij));
        const float4 dyU = __ldg((const float4*)(dY + um));
        const float4 byC = __ldg((const float4*)(bY + ij));
        const float4 byU = __ldg((const float4*)(bY + um));

        const float dxb[5] = {dxL - bxL, dxC.x - bxC.x, dxC.y - bxC.y,
                              dxC.z - bxC.z, dxC.w - bxC.w};
        const float dybC[4] = {dyC.x - byC.x, dyC.y - byC.y,
                               dyC.z - byC.z, dyC.w - byC.w};
        const float dybU[4] = {dyU.x - byU.x, dyU.y - byU.y,
                               dyU.z - byU.z, dyU.w - byU.w};

        float4 r;
        float* rp = &r.x;
#pragma unroll
        for (int t = 0; t < 4; ++t) {
            float conv = fmaf(up[t], w8, up[t + 1] * w7);
            conv = fmaf(up[t + 2], w6, conv);
            conv = fmaf(md[t], w5, conv);
            conv = fmaf(md[t + 1], w4, conv);
            conv = fmaf(md[t + 2], w3, conv);
            conv = fmaf(dn[t], w2, conv);
            conv = fmaf(dn[t + 1], w1, conv);
            conv = fmaf(dn[t + 2], w0, conv);
            const float se = sigma * ((dxb[t] - dxb[t + 1]) +
                                      (dybU[t] - dybC[t]));
            rp[t] = fmaf(alpha, conv, se);
        }
        *(float4*)(base + ij) = r;
    } else {
#pragma unroll
        for (int t = 0; t < 4; ++t) {
            const int jj = j + t;
            const int idx = i * WW + jj;
            const int jm = (jj - 1) & MW, im = (i - 1) & MW;
            float dxb_c = __ldg(&dX[idx]) - __ldg(&bX[idx]);
            float dxb_l = __ldg(&dX[i * WW + jm]) - __ldg(&bX[i * WW + jm]);
            float dyb_c = __ldg(&dY[idx]) - __ldg(&bY[idx]);
            float dyb_u = __ldg(&dY[im * WW + jj]) - __ldg(&bY[im * WW + jj]);
            float se = sigma * ((dxb_l - dxb_c) + (dyb_u - dyb_c));
            float conv = 0.f;
#pragma unroll
            for (int p = 0; p < 3; ++p) {
                const int r_ = (i + p - 1) & MW;
#pragma unroll
                for (int q = 0; q < 3; ++q) {
                    const int c = (jj + q - 1) & MW;
                    conv = fmaf(__ldg(&STg[r_ * WW + c]),
                                __ldg(&w9[(2 - p) * 3 + (2 - q)]), conv);
                }
            }
            base[idx] = fmaf(alpha, conv, se);
        }
    }
}

// ---------------------------------------------------------------------------
// One fused _compute iteration: 15-row x 6-col rolling window per vertical
// run of 6 quads. Valid slot range iter K: a,b in [K, 74-K].
// K==1 also initializes fa from the in-window quad values (g0 * base0).
// Patch columns: index c = global col - (gx0-12); window base col = 2b (even).
// ---------------------------------------------------------------------------
template <int K>
__device__ __forceinline__ void iter_step(
    const float* __restrict__ in, float* __restrict__ out,
    float* __restrict__ FA,
    int wio, int a0, int b, int nPack, int mPack, int fmPack, float* fa,
    float w0, float w1, float w2, float w3, float w4,
    float w5, float w6, float w7, float w8,
    float alpha, float bs, float g, float g0)
{
    const float* p = in + wio;

    // Prologue: rows 2a0-1, 2a0, 2a0+1, top corners.
    const float2 L0 = lds2(p),          M0f = lds2(p + 2),      R0 = lds2(p + 4);
    const float2 L1 = lds2(p + BP),     M1f = lds2(p + BP + 2), R1 = lds2(p + BP + 4);
    float2 L_c = lds2(p + 2 * BP);
    float2 M_c = lds2(p + 2 * BP + 2);
    float2 R_c = lds2(p + 2 * BP + 4);

    float oTa = CORR9(L0.y, M0f.x, M0f.y, L1.y, M1f.x, M1f.y,
                      L_c.y, M_c.x, M_c.y);
    float oTb = CORR9(M0f.y, R0.x, R0.y, M1f.y, R1.x, R1.y,
                      M_c.y, R_c.x, R_c.y);

    float2 M_a = M0f;
    float  lA = L1.y, rA = R1.x;
    float2 M_b = M1f;

#pragma unroll
    for (int k = 0; k < 6; ++k) {
        const float* q = p + (2 * k + 3) * BP;
        const float2 L3 = lds2(q),      M3 = lds2(q + 2),      R3 = lds2(q + 4);
        const float2 L4 = lds2(q + BP), M4 = lds2(q + BP + 2), R4 = lds2(q + BP + 4);

        const float oBa = CORR9(L_c.y, M_c.x, M_c.y, L3.y, M3.x, M3.y,
                                L4.y, M4.x, M4.y);
        const float oBb = CORR9(M_c.y, R_c.x, R_c.y, M3.y, R3.x, R3.y,
                                M4.y, R4.x, R4.y);

        const float lap00 = 4.f * M_b.x - lA - M_b.y - M_a.x - M_c.x;
        const float lap01 = 4.f * M_b.y - M_b.x - rA - M_a.y - M_c.y;
        const float lap10 = 4.f * M_c.x - L_c.y - M_c.y - M_b.x - M3.x;
        const float lap11 = 4.f * M_c.y - M_c.x - R_c.x - M_b.y - M3.y;

        const float r00 = fmaf(alpha, oTa * w4, bs * lap00);
        const float r01 = fmaf(alpha, fmaf(oTa, w5, oTb * w3), bs * lap01);
        const float r10 = fmaf(alpha, fmaf(oTa, w7, oBa * w1), bs * lap10);
        const float r11 = fmaf(alpha,
            fmaf(oTa, w8, fmaf(oTb, w6, fmaf(oBa, w2, oBb * w0))),
            bs * lap11);

        if (K < 5) {
            const int n = (nPack >> (5 * k)) & 31;
            float* ob = out + wio + (2 * k + 1) * BP + 2;   // pixel (2a,2b)
            if (n >= K) {                       // full interior quad (common)
                sts2(ob, r00, r01);
                sts2(ob + BP, r10, r11);
            } else {
                const int m = (mPack >> (5 * k)) & 31;
                if (m >= K) {                   // partial edge quad (rare)
                    const int a = a0 + k;
                    const bool ch = (b <= 73 - K), rh = (a <= 73 - K);
                    ob[0] = r00;
                    if (ch) ob[1] = r01;
                    if (rh) { ob[BP] = r10; if (ch) ob[BP + 1] = r11; }
                }
            }
            if (K == 1) {
                // fa init folded in: quad values of `in` are M_b (row 2a)
                // and M_c (row 2a+1), cols 2b..2b+1.
                fa[4 * k + 0] = fmaf(g, r00, g0 * M_b.x);
                fa[4 * k + 1] = fmaf(g, r01, g0 * M_b.y);
                fa[4 * k + 2] = fmaf(g, r10, g0 * M_c.x);
                fa[4 * k + 3] = fmaf(g, r11, g0 * M_c.y);
            } else {
                fa[4 * k + 0] = fmaf(g, r00, fa[4 * k + 0]);
                fa[4 * k + 1] = fmaf(g, r01, fa[4 * k + 1]);
                fa[4 * k + 2] = fmaf(g, r10, fa[4 * k + 2]);
                fa[4 * k + 3] = fmaf(g, r11, fa[4 * k + 3]);
            }
        } else {
            const int fm = (fmPack >> (4 * k)) & 15;
            if (fm) {
                const int a = a0 + k;
                float* fp = FA + (2 * a - 10) * FAP + (2 * b - 10);
                const float v00 = fmaf(g, r00, fa[4 * k + 0]);
                const float v01 = fmaf(g, r01, fa[4 * k + 1]);
                const float v10 = fmaf(g, r10, fa[4 * k + 2]);
                const float v11 = fmaf(g, r11, fa[4 * k + 3]);
                const bool r0ok = fm & 1, r1ok = fm & 2;
                const bool c0ok = fm & 4, c1ok = fm & 8;
                if (r0ok) {
                    if (c0ok && c1ok) sts2(fp, v00, v01);
                    else { if (c0ok) fp[0] = v00; if (c1ok) fp[1] = v01; }
                }
                if (r1ok) {
                    if (c0ok && c1ok) sts2(fp + FAP, v10, v11);
                    else { if (c0ok) fp[FAP] = v10; if (c1ok) fp[FAP + 1] = v11; }
                }
            }
        }

        // Roll window down 2 rows
        M_a = M_c;
        lA = L3.y; M_b = M3; rA = R3.x;
        L_c = L4; M_c = M4; R_c = R4;
        oTa = oBa; oTb = oBb;
    }
    __syncthreads();
}

// ---------------------------------------------------------------------------
// Mega kernel: 5 fused iterations + shrink epilogue, 128x128 core per block.
// ---------------------------------------------------------------------------
__global__ __launch_bounds__(NT, 1) void mega_kernel(
    const float* __restrict__ base0, const float* __restrict__ bX,
    const float* __restrict__ bY, const float* __restrict__ alpha_p,
    const float* __restrict__ beta0_p, const float* __restrict__ beta1_p,
    const float* __restrict__ sigma_p, const float* __restrict__ gamma,
    const float* __restrict__ w9, float* __restrict__ out)
{
    extern __shared__ __align__(16) float sm[];
    float* A  = sm;                 // 149*152
    float* B  = A + ASIZE;          // 149*152 (+GUARD slack for gated reads)
    float* FA = B;                  // aliases B (dead after iter 4); 129x132

    const int tid = threadIdx.x;
    const int gx0 = blockIdx.x * CORE;
    const int gy0 = blockIdx.y * CORE;

    const float w0 = __ldg(&w9[0]), w1 = __ldg(&w9[1]), w2 = __ldg(&w9[2]);
    const float w3 = __ldg(&w9[3]), w4 = __ldg(&w9[4]), w5 = __ldg(&w9[5]);
    const float w6 = __ldg(&w9[6]), w7 = __ldg(&w9[7]), w8 = __ldg(&w9[8]);
    const float alpha = __ldg(alpha_p);
    const float bs = __ldg(beta0_p) + __ldg(sigma_p);

    // --- run precompute: vertical run of 6 quads (a0..a0+5, b) -------------
    int wio, a0, bq, nPack = 0, mPack = 0, fmPack = 0;
    if (tid < NRUN) {
        const int rr = tid / 73;          // 0..12
        bq = tid - rr * 73 + 1;           // 1..73
        a0 = 6 * rr + 1;                  // 1,7,...,73
        wio = (2 * a0 - 1) * BP + 2 * bq;
#pragma unroll
        for (int k = 0; k < 6; ++k) {
            const int a = a0 + k;         // up to 78; a>73 fully gated
            int n = max(0, min(min(a, bq), min(73 - a, 73 - bq)));
            int m = max(0, min(min(a, bq), min(74 - a, 74 - bq)));
            n = min(n, 31); m = min(m, 31);
            const int fm = ((a >= 5 && a <= 69) ? 1 : 0) |
                           ((a >= 5 && a <= 68) ? 2 : 0) |
                           ((bq >= 5 && bq <= 69) ? 4 : 0) |
                           ((bq >= 5 && bq <= 68) ? 8 : 0);
            nPack |= n << (5 * k);
            mPack |= m << (5 * k);
            fmPack |= fm << (4 * k);
        }
    } else {
        wio = 0; a0 = 1; bq = 1;
    }

    // --- load 149x152 base0 patch (cols gx0-12 .. gx0+139, 38 f4/row) ------
    const bool interior = (blockIdx.x >= 1) & (blockIdx.x <= gridDim.x - 2) &
                          (blockIdx.y >= 1) & (blockIdx.y <= gridDim.y - 2);
    if (interior) {
        const float* src = base0 + (gy0 - 10) * WW + (gx0 - 12);
        for (int idx = tid; idx < B0 * 38; idx += NT) {
            const int r = idx / 38;
            const int c4 = idx - r * 38;
            const float4 v = __ldg((const float4*)(src + r * WW + 4 * c4));
            *(float4*)(A + r * BP + 4 * c4) = v;
        }
    } else {
        for (int idx = tid; idx < B0 * BP; idx += NT) {
            const int r = idx / BP;
            const int c = idx - r * BP;
            A[r * BP + c] = __ldg(&base0[((gy0 - 10 + r) & MW) * WW +
                                         ((gx0 - 12 + c) & MW)]);
        }
    }
    __syncthreads();

    float fa[24];
    const float g0 = __ldg(&gamma[0]);

    iter_step<1>(A, B, FA, wio, a0, bq, nPack, mPack, fmPack, fa,
                 w0, w1, w2, w3, w4, w5, w6, w7, w8, alpha, bs,
                 __ldg(&gamma[1]), g0);
    iter_step<2>(B, A, FA, wio, a0, bq, nPack, mPack, fmPack, fa,
                 w0, w1, w2, w3, w4, w5, w6, w7, w8, alpha, bs,
                 __ldg(&gamma[2]), g0);
    iter_step<3>(A, B, FA, wio, a0, bq, nPack, mPack, fmPack, fa,
                 w0, w1, w2, w3, w4, w5, w6, w7, w8, alpha, bs,
                 __ldg(&gamma[3]), g0);
    iter_step<4>(B, A, FA, wio, a0, bq, nPack, mPack, fmPack, fa,
                 w0, w1, w2, w3, w4, w5, w6, w7, w8, alpha, bs,
                 __ldg(&gamma[4]), g0);
    // iter 5 reads A; writes f directly into FA (=B, dead since iter-4 sync)
    iter_step<5>(A, B, FA, wio, a0, bq, nPack, mPack, fmPack, fa,
                 w0, w1, w2, w3, w4, w5, w6, w7, w8, alpha, bs,
                 __ldg(&gamma[5]), g0);

    // --- shrink / Bregman epilogue: 4 pixels per step (float4) -------------
    const float thr = __fdividef(__ldg(beta1_p), __ldg(sigma_p));
    for (int idx = tid; idx < 128 * 32; idx += NT) {
        const int r = idx >> 5;
        const int cp = idx & 31;
        const float* fr0 = FA + r * FAP + 4 * cp;
        const float4 f0 = *(const float4*)(fr0);
        const float  fR = fr0[4];
        const float4 f1 = *(const float4*)(fr0 + FAP);
        const float fc[5] = {f0.x, f0.y, f0.z, f0.w, fR};
        const float fd[4] = {f1.x, f1.y, f1.z, f1.w};
        const int ij = (gy0 + r) * WW + gx0 + 4 * cp;
        const float4 bx = __ldg((const float4*)(bX + ij));
        const float4 by = __ldg((const float4*)(bY + ij));
        const float bxs[4] = {bx.x, bx.y, bx.z, bx.w};
        const float bys[4] = {by.x, by.y, by.z, by.w};

        float4 oDx, oDy, oBx, oBy;
        float* pDx = &oDx.x; float* pDy = &oDy.x;
        float* pBx = &oBx.x; float* pBy = &oBy.x;
#pragma unroll
        for (int t = 0; t < 4; ++t) {
            const float dxf = fc[t + 1] - fc[t];
            const float dyf = fd[t] - fc[t];
            const float px = dxf + bxs[t];
            const float py = dyf + bys[t];
            const float nn = sqrtf(fmaf(px, px, py * py));
            const float sh = __fdividef(fmaxf(nn - thr, 0.f), nn + 1e-8f);
            const float dxn = px * sh;
            const float dyn = py * sh;
            pDx[t] = dxn;
            pDy[t] = dyn;
            pBx[t] = bxs[t] + dxf - dxn;
            pBy[t] = bys[t] + dyf - dyn;
        }
        *(float4*)(out + ij) = f0;
        *(float4*)(out + NPIX + ij) = oDx;
        *(float4*)(out + 2 * NPIX + ij) = oDy;
        *(float4*)(out + 3 * NPIX + ij) = oBx;
        *(float4*)(out + 4 * NPIX + ij) = oBy;
    }
}

static const int SMEM_BYTES = (2 * ASIZE + GUARD) * 4;

extern "C" void kernel_launch(void* const* d_in, const int* in_sizes, int n_in,
                              void* d_out, int out_size)
{
    const float* STg   = (const float*)d_in[0];
    const float* dX    = (const float*)d_in[1];
    const float* dY    = (const float*)d_in[2];
    const float* bX    = (const float*)d_in[3];
    const float* bY    = (const float*)d_in[4];
    const float* alpha = (const float*)d_in[7];
    const float* beta0 = (const float*)d_in[8];
    const float* beta1 = (const float*)d_in[9];
    const float* sigma = (const float*)d_in[10];
    const float* gamma = (const float*)d_in[11];
    const float* w9    = (const float*)d_in[12];

    float* out = (float*)d_out;

    float* pB0;
    cudaGetSymbolAddress((void**)&pB0, g_base0);

    dim3 b1(32, 8), g1(WW / 128, HH / 8);
    stage0_kernel<<<g1, b1>>>(STg, dX, dY, bX, bY, alpha, sigma, w9, pB0);

    cudaFuncSetAttribute(mega_kernel,
                         cudaFuncAttributeMaxDynamicSharedMemorySize,
                         SMEM_BYTES);
    dim3 g2(WW / CORE, HH / CORE);
    mega_kernel<<<g2, NT, SMEM_BYTES>>>(pB0, bX, bY, alpha, beta0, beta1,
                                        sigma, gamma, w9, out);
}